// round 9
// baseline (speedup 1.0000x reference)
#include <cuda_runtime.h>
#include <cuda_bf16.h>
#include <math.h>
#include <stdint.h>

// Problem shape (fixed by setup_inputs)
#define N_FEAT  32768
#define M_PROTO 2048
#define K_DIM   512

// ---------------------------------------------------------------------------
// Static device scratch (no cudaMalloc allowed)
// gXhi32: tf32-valued fp32, k-permuted per 8 (phys j = logical {0,4,1,5,2,6,3,7})
// gXhibf/gXlobf: bf16 hi/lo, UNPERMUTED (canonical k order, for ldmatrix)
// ---------------------------------------------------------------------------
__device__ float         gAhi32[(size_t)N_FEAT * K_DIM];
__device__ float         gBhi32[(size_t)M_PROTO * K_DIM];
__device__ __nv_bfloat16 gAhibf[(size_t)N_FEAT * K_DIM];
__device__ __nv_bfloat16 gAlobf[(size_t)N_FEAT * K_DIM];
__device__ __nv_bfloat16 gBhibf[(size_t)M_PROTO * K_DIM];
__device__ __nv_bfloat16 gBlobf[(size_t)M_PROTO * K_DIM];
__device__ float g_psq10[M_PROTO];      // 10 * ||p_m||^2

// ---------------------------------------------------------------------------
__device__ __forceinline__ uint32_t smem_u32(const void* p) {
    uint32_t a;
    asm("{ .reg .u64 t; cvta.to.shared.u64 t, %1; cvt.u32.u64 %0, t; }" : "=r"(a) : "l"(p));
    return a;
}
#define CP_ASYNC16(dst, src) \
    asm volatile("cp.async.cg.shared.global [%0], [%1], 16;" :: "r"(dst), "l"(src) : "memory")
#define CP_COMMIT() asm volatile("cp.async.commit_group;" ::: "memory")
#define CP_WAIT(n)  asm volatile("cp.async.wait_group %0;" :: "n"(n) : "memory")

__device__ __forceinline__ uint32_t f2tf32(float x) {
    uint32_t r;
    asm("cvt.rna.tf32.f32 %0, %1;" : "=r"(r) : "f"(x));
    return r;
}

// mma.sync m16n8k8 tf32 (sm_80 baseline -> legal on plain sm_100)
__device__ __forceinline__ void mma_tf32(float* d,
                                         uint32_t a0, uint32_t a1, uint32_t a2, uint32_t a3,
                                         uint32_t b0, uint32_t b1) {
    asm volatile(
        "mma.sync.aligned.m16n8k8.row.col.f32.tf32.tf32.f32 "
        "{%0,%1,%2,%3}, {%4,%5,%6,%7}, {%8,%9}, {%0,%1,%2,%3};"
        : "+f"(d[0]), "+f"(d[1]), "+f"(d[2]), "+f"(d[3])
        : "r"(a0), "r"(a1), "r"(a2), "r"(a3), "r"(b0), "r"(b1));
}

// mma.sync m16n8k16 bf16 (sm_80 baseline)
__device__ __forceinline__ void mma_bf16(float* d,
                                         uint32_t a0, uint32_t a1, uint32_t a2, uint32_t a3,
                                         uint32_t b0, uint32_t b1) {
    asm volatile(
        "mma.sync.aligned.m16n8k16.row.col.f32.bf16.bf16.f32 "
        "{%0,%1,%2,%3}, {%4,%5,%6,%7}, {%8,%9}, {%0,%1,%2,%3};"
        : "+f"(d[0]), "+f"(d[1]), "+f"(d[2]), "+f"(d[3])
        : "r"(a0), "r"(a1), "r"(a2), "r"(a3), "r"(b0), "r"(b1));
}

__device__ __forceinline__ void ldm_x4(uint32_t addr, uint32_t* r) {
    asm volatile("ldmatrix.sync.aligned.m8n8.x4.shared.b16 {%0,%1,%2,%3}, [%4];"
        : "=r"(r[0]), "=r"(r[1]), "=r"(r[2]), "=r"(r[3]) : "r"(addr));
}

// ---------------------------------------------------------------------------
// Split fp32 -> tf32 hi (fp32, permuted per 8) + bf16(hi), bf16(lo) canonical.
// One thread = 16 consecutive k of one row.
// ---------------------------------------------------------------------------
__global__ void split_kernel(const float* __restrict__ src, int ngroups, int which) {
    float*         hi32 = which ? gBhi32 : gAhi32;
    __nv_bfloat16* hibf = which ? gBhibf : gAhibf;
    __nv_bfloat16* lobf = which ? gBlobf : gAlobf;
    int g = blockIdx.x * blockDim.x + threadIdx.x;
    if (g >= ngroups) return;

    const float4* s4 = (const float4*)(src + (size_t)g * 16);
    float in[16];
    float4 x0 = s4[0], x1 = s4[1], x2 = s4[2], x3 = s4[3];
    in[0]=x0.x; in[1]=x0.y; in[2]=x0.z; in[3]=x0.w;
    in[4]=x1.x; in[5]=x1.y; in[6]=x1.z; in[7]=x1.w;
    in[8]=x2.x; in[9]=x2.y; in[10]=x2.z; in[11]=x2.w;
    in[12]=x3.x; in[13]=x3.y; in[14]=x3.z; in[15]=x3.w;

    float h[16], l[16];
#pragma unroll
    for (int i = 0; i < 16; i++) {
        h[i] = __uint_as_float(f2tf32(in[i]));
        l[i] = in[i] - h[i];
    }

    // fp32 hi, permuted per 8: phys j holds logical {0,4,1,5,2,6,3,7}[j]
    float4 o0 = {h[0], h[4], h[1], h[5]};
    float4 o1 = {h[2], h[6], h[3], h[7]};
    float4 o2 = {h[8], h[12], h[9], h[13]};
    float4 o3 = {h[10], h[14], h[11], h[15]};
    float4* d4 = (float4*)(hi32 + (size_t)g * 16);
    d4[0] = o0; d4[1] = o1; d4[2] = o2; d4[3] = o3;

    // bf16: canonical order
    __nv_bfloat162 wh[8], wl[8];
#pragma unroll
    for (int j = 0; j < 8; j++) {
        wh[j] = __floats2bfloat162_rn(h[2 * j], h[2 * j + 1]);
        wl[j] = __floats2bfloat162_rn(l[2 * j], l[2 * j + 1]);
    }
    uint4* dh = (uint4*)(hibf + (size_t)g * 16);
    uint4* dl = (uint4*)(lobf + (size_t)g * 16);
    dh[0] = *(uint4*)&wh[0]; dh[1] = *(uint4*)&wh[4];
    dl[0] = *(uint4*)&wl[0]; dl[1] = *(uint4*)&wl[4];
}

// ---------------------------------------------------------------------------
// 10*||p_m||^2, one warp per row
// ---------------------------------------------------------------------------
__global__ void psq_kernel(const float* __restrict__ B) {
    int w = (blockIdx.x * blockDim.x + threadIdx.x) >> 5;
    int lane = threadIdx.x & 31;
    if (w >= M_PROTO) return;
    const float4* row = (const float4*)(B + (size_t)w * K_DIM);
    float s = 0.f;
#pragma unroll
    for (int i = 0; i < 4; i++) {
        float4 v = row[lane + i * 32];
        s += v.x * v.x + v.y * v.y + v.z * v.z + v.w * v.w;
    }
#pragma unroll
    for (int o = 16; o > 0; o >>= 1) s += __shfl_xor_sync(0xFFFFFFFFu, s, o);
    if (lane == 0) g_psq10[w] = 10.f * s;
}

// ---------------------------------------------------------------------------
// GEMM: S[n,m] = 20 * dot(feat_n, proto_m) - 10*||p_m||^2
// Hybrid emulation: hi*hi in tf32 (exact), cross terms hi*lo + lo*hi in bf16
// via ldmatrix fragments (minimal non-MMA instruction count).
// CTA 128x128, BK=16, 2-stage cp.async ring.
// Stage layout (words): A32[0,3072) stride24 | B32[3072,6144) stride24 |
//   Ahibf[6144,7168) | Alobf[7168,8192) | Bhibf[8192,9216) | Blobf[9216,10240)
// bf16 tiles: 128 rows x 16 bf16; 16B-unit index u(row,kh)=row*2+(kh^((row>>2)&1))
// ---------------------------------------------------------------------------
#define STAGE_W   10240
#define STAGE_B   (STAGE_W * 4)
#define SMEM_TOT  (2 * STAGE_B)           // 81920 bytes
#define KT_STEPS  (K_DIM / 16)            // 32

__global__ __launch_bounds__(256, 1)
void gemm_tc_kernel(float* __restrict__ S) {
    extern __shared__ float smem[];
    const uint32_t smem_base = smem_u32(smem);
    const int tid  = threadIdx.x;
    const int wid  = tid >> 5;
    const int lane = tid & 31;
    const int warpM = wid & 1;            // 2 warps in M (feat)
    const int warpN = wid >> 1;           // 4 warps in N (proto)
    const int m0 = blockIdx.x * 128;
    const int n0 = blockIdx.y * 128;

    float acc[4][4][4];
#pragma unroll
    for (int i = 0; i < 4; i++)
#pragma unroll
        for (int j = 0; j < 4; j++)
#pragma unroll
            for (int q = 0; q < 4; q++) acc[i][j][q] = 0.f;

    // ---- stage loader: 8 cp.async(16B) per thread ----
    auto load_stage = [&](int buf, int kt) {
        uint32_t sb = smem_base + (uint32_t)buf * STAGE_B;
#pragma unroll
        for (int it = 0; it < 8; it++) {
            int chunk = tid + it * 256;
            if (it < 2) {
                int c = chunk;                       // A hi32: 512 chunks
                int row = c >> 2, j = c & 3;
                uint32_t dst = sb + (uint32_t)(row * 24 + j * 4) * 4u;
                const float* src = gAhi32 + (size_t)(n0 + row) * K_DIM + kt * 16 + j * 4;
                CP_ASYNC16(dst, src);
            } else if (it < 4) {
                int c = chunk - 512;                 // B hi32: 512 chunks
                int row = c >> 2, j = c & 3;
                uint32_t dst = sb + (uint32_t)(3072 + row * 24 + j * 4) * 4u;
                const float* src = gBhi32 + (size_t)(m0 + row) * K_DIM + kt * 16 + j * 4;
                CP_ASYNC16(dst, src);
            } else {
                int idx = chunk - 1024;              // bf16: 4 tiles x 256 chunks
                int arr = idx >> 8;                  // 0:Ahibf 1:Alobf 2:Bhibf 3:Blobf
                int cc  = idx & 255;
                int row = cc >> 1, kh = cc & 1;
                uint32_t u = (uint32_t)(row * 2 + (kh ^ ((row >> 2) & 1)));
                uint32_t dst = sb + (uint32_t)(6144 + arr * 1024) * 4u + u * 16u;
                const char* srcb;
                if (arr == 0)
                    srcb = (const char*)gAhibf + ((size_t)(n0 + row) * K_DIM + kt * 16) * 2 + kh * 16;
                else if (arr == 1)
                    srcb = (const char*)gAlobf + ((size_t)(n0 + row) * K_DIM + kt * 16) * 2 + kh * 16;
                else if (arr == 2)
                    srcb = (const char*)gBhibf + ((size_t)(m0 + row) * K_DIM + kt * 16) * 2 + kh * 16;
                else
                    srcb = (const char*)gBlobf + ((size_t)(m0 + row) * K_DIM + kt * 16) * 2 + kh * 16;
                CP_ASYNC16(dst, srcb);
            }
        }
        CP_COMMIT();
    };

    load_stage(0, 0);
    load_stage(1, 1);

    const int r  = lane >> 2;
    const int c2 = (lane & 3) * 2;

    // per-lane ldmatrix byte offsets within a bf16 tile
    // A (x4 = m16 x k16): matrix j = lane>>3: row=(j&1)*8+(lane&7), kh=j>>1
    const int rowA = ((lane >> 3) & 1) * 8 + (lane & 7);
    const int khA  = (lane >> 4) & 1;
    const uint32_t offA = (uint32_t)(rowA * 2 + (khA ^ ((rowA >> 2) & 1))) * 16u;
    // B (x4 = two n8 x k16): matrix j: row=(j>>1)*8+(lane&7), kh=j&1
    const int rowB = ((lane >> 4) & 1) * 8 + (lane & 7);
    const int khB  = (lane >> 3) & 1;
    const uint32_t offB = (uint32_t)(rowB * 2 + (khB ^ ((rowB >> 2) & 1))) * 16u;

    const uint32_t aAoff = 6144u * 4u + (uint32_t)(warpM * 64) * 32u + offA;
    const uint32_t aBoff = 8192u * 4u + (uint32_t)(warpN * 32) * 32u + offB;

    for (int kt = 0; kt < KT_STEPS; kt++) {
        const int b = kt & 1;
        CP_WAIT(1);
        __syncthreads();

        const uint32_t sb = smem_base + (uint32_t)b * STAGE_B;
        const float* st = smem + b * STAGE_W;

        // ---- bf16 fragments via ldmatrix ----
        uint32_t AH[4][4], AL[4][4], BH[2][4], BL[2][4];
        const uint32_t aA = sb + aAoff;
        const uint32_t aB = sb + aBoff;
#pragma unroll
        for (int np = 0; np < 2; np++) {
            ldm_x4(aB + np * 512, BH[np]);
            ldm_x4(aB + 4096 + np * 512, BL[np]);
        }
#pragma unroll
        for (int mt = 0; mt < 4; mt++) {
            ldm_x4(aA + mt * 512, AH[mt]);
            ldm_x4(aA + 4096 + mt * 512, AL[mt]);
        }

        // ---- bf16 cross-term MMAs ----
#pragma unroll
        for (int mt = 0; mt < 4; mt++)
#pragma unroll
            for (int np = 0; np < 2; np++) {
                mma_bf16(acc[mt][2 * np], AH[mt][0], AH[mt][1], AH[mt][2], AH[mt][3],
                         BL[np][0], BL[np][1]);
                mma_bf16(acc[mt][2 * np], AL[mt][0], AL[mt][1], AL[mt][2], AL[mt][3],
                         BH[np][0], BH[np][1]);
                mma_bf16(acc[mt][2 * np + 1], AH[mt][0], AH[mt][1], AH[mt][2], AH[mt][3],
                         BL[np][2], BL[np][3]);
                mma_bf16(acc[mt][2 * np + 1], AL[mt][0], AL[mt][1], AL[mt][2], AL[mt][3],
                         BH[np][2], BH[np][3]);
            }

        // ---- tf32 hi*hi (two k8 steps, affine LDS) ----
#pragma unroll
        for (int ko = 0; ko < 2; ko++) {
            const int kb = ko * 8 + c2;
            uint2 BT[4];
#pragma unroll
            for (int nt = 0; nt < 4; nt++) {
                int col = warpN * 32 + nt * 8 + r;
                BT[nt] = *(const uint2*)(st + 3072 + col * 24 + kb);
            }
#pragma unroll
            for (int mt = 0; mt < 4; mt++) {
                int row = warpM * 64 + mt * 16 + r;
                uint2 a0 = *(const uint2*)(st + row * 24 + kb);
                uint2 a1 = *(const uint2*)(st + (row + 8) * 24 + kb);
#pragma unroll
                for (int nt = 0; nt < 4; nt++)
                    mma_tf32(acc[mt][nt], a0.x, a1.x, a0.y, a1.y, BT[nt].x, BT[nt].y);
            }
        }

        __syncthreads();
        if (kt + 2 < KT_STEPS) load_stage(b, kt + 2);
    }

    // ---- epilogue ----
    float* sp = smem;
    __syncthreads();
    if (tid < 128) sp[tid] = g_psq10[m0 + tid];
    __syncthreads();

#pragma unroll
    for (int mt = 0; mt < 4; mt++) {
        int gr = n0 + warpM * 64 + mt * 16 + r;
#pragma unroll
        for (int nt = 0; nt < 4; nt++) {
            int lc = warpN * 32 + nt * 8 + c2;
            float p0 = sp[lc], p1 = sp[lc + 1];
            float2 o0, o1;
            o0.x = 20.f * acc[mt][nt][0] - p0;
            o0.y = 20.f * acc[mt][nt][1] - p1;
            o1.x = 20.f * acc[mt][nt][2] - p0;
            o1.y = 20.f * acc[mt][nt][3] - p1;
            *(float2*)(S + (size_t)gr * M_PROTO + m0 + lc) = o0;
            *(float2*)(S + (size_t)(gr + 8) * M_PROTO + m0 + lc) = o1;
        }
    }
}

// ---------------------------------------------------------------------------
// Row softmax (in place), quality = 1/sum(exp), max_id = first argmax
// ---------------------------------------------------------------------------
__global__ void softmax_kernel(float* __restrict__ S,
                               float* __restrict__ quality,
                               float* __restrict__ maxid) {
    const int row = blockIdx.x;
    float* srow = S + (size_t)row * M_PROTO;
    const int t = threadIdx.x;

    float v[8];
    float4 v0 = *(const float4*)(srow + t * 8 + 0);
    float4 v1 = *(const float4*)(srow + t * 8 + 4);
    v[0] = v0.x; v[1] = v0.y; v[2] = v0.z; v[3] = v0.w;
    v[4] = v1.x; v[5] = v1.y; v[6] = v1.z; v[7] = v1.w;

    float lmax = v[0];
    int   limx = t * 8;
#pragma unroll
    for (int j = 1; j < 8; j++)
        if (v[j] > lmax) { lmax = v[j]; limx = t * 8 + j; }

    __shared__ float smax[256];
    __shared__ int   sidx[256];
    smax[t] = lmax;
    sidx[t] = limx;
    __syncthreads();
#pragma unroll
    for (int s = 128; s > 0; s >>= 1) {
        if (t < s) {
            float v2 = smax[t + s];
            int   i2 = sidx[t + s];
            if (v2 > smax[t] || (v2 == smax[t] && i2 < sidx[t])) {
                smax[t] = v2; sidx[t] = i2;
            }
        }
        __syncthreads();
    }
    const float rowmax = smax[0];
    const int   rowarg = sidx[0];
    __syncthreads();

    float e[8];
    float lsum = 0.f;
#pragma unroll
    for (int j = 0; j < 8; j++) { e[j] = expf(v[j] - rowmax); lsum += e[j]; }
    smax[t] = lsum;
    __syncthreads();
#pragma unroll
    for (int s = 128; s > 0; s >>= 1) {
        if (t < s) smax[t] += smax[t + s];
        __syncthreads();
    }
    const float inv = 1.0f / smax[0];

    float4 o0, o1;
    o0.x = e[0] * inv; o0.y = e[1] * inv; o0.z = e[2] * inv; o0.w = e[3] * inv;
    o1.x = e[4] * inv; o1.y = e[5] * inv; o1.z = e[6] * inv; o1.w = e[7] * inv;
    *(float4*)(srow + t * 8 + 0) = o0;
    *(float4*)(srow + t * 8 + 4) = o1;

    if (t == 0) {
        quality[row] = inv;
        maxid[row]   = (float)rowarg;
    }
}

// ---------------------------------------------------------------------------
extern "C" void kernel_launch(void* const* d_in, const int* in_sizes, int n_in,
                              void* d_out, int out_size) {
    const float* feat  = (const float*)d_in[0];   // [32768, 512]
    const float* proto = (const float*)d_in[1];   // [2048, 512]
    float* out = (float*)d_out;

    float* quality = out;
    float* maxid   = out + N_FEAT;
    float* pred    = out + 2 * N_FEAT;

    cudaFuncSetAttribute(gemm_tc_kernel,
                         cudaFuncAttributeMaxDynamicSharedMemorySize, SMEM_TOT);

    int gA = N_FEAT * K_DIM / 16;
    int gB = M_PROTO * K_DIM / 16;
    split_kernel<<<(gA + 255) / 256, 256>>>(feat, gA, 0);
    split_kernel<<<(gB + 255) / 256, 256>>>(proto, gB, 1);
    psq_kernel<<<M_PROTO / 8, 256>>>(proto);

    dim3 grid(M_PROTO / 128, N_FEAT / 128);
    gemm_tc_kernel<<<grid, 256, SMEM_TOT>>>(pred);

    softmax_kernel<<<N_FEAT, 256>>>(pred, quality, maxid);
}

// round 10
// speedup vs baseline: 1.5622x; 1.5622x over previous
#include <cuda_runtime.h>
#include <cuda_fp16.h>
#include <math.h>
#include <stdint.h>

// Problem shape (fixed by setup_inputs)
#define N_FEAT  32768
#define M_PROTO 2048
#define K_DIM   512

// ---------------------------------------------------------------------------
// Static device scratch (no cudaMalloc allowed)
// fp16 double-split (x = h0 + h1), pair-permuted per 16-k group:
// phys pair slot j holds logical pair pp[j], pp = {0,4,1,5,2,6,3,7}
// => 8B unit q = logical pairs (q, q+4) = exactly one mma fragment (a0,a2)
// ---------------------------------------------------------------------------
__device__ __half gAh0[(size_t)N_FEAT * K_DIM];
__device__ __half gAh1[(size_t)N_FEAT * K_DIM];
__device__ __half gBh0[(size_t)M_PROTO * K_DIM];
__device__ __half gBh1[(size_t)M_PROTO * K_DIM];
__device__ float g_psq10[M_PROTO];      // 10 * ||p_m||^2

// ---------------------------------------------------------------------------
__device__ __forceinline__ uint32_t smem_u32(const void* p) {
    uint32_t a;
    asm("{ .reg .u64 t; cvta.to.shared.u64 t, %1; cvt.u32.u64 %0, t; }" : "=r"(a) : "l"(p));
    return a;
}
#define CP_ASYNC16(dst, src) \
    asm volatile("cp.async.cg.shared.global [%0], [%1], 16;" :: "r"(dst), "l"(src) : "memory")
#define CP_COMMIT() asm volatile("cp.async.commit_group;" ::: "memory")
#define CP_WAIT(n)  asm volatile("cp.async.wait_group %0;" :: "n"(n) : "memory")

// mma.sync m16n8k16 fp16 with fp32 accumulate (sm_80 baseline)
__device__ __forceinline__ void mma_f16(float* d,
                                        uint32_t a0, uint32_t a1, uint32_t a2, uint32_t a3,
                                        uint32_t b0, uint32_t b1) {
    asm volatile(
        "mma.sync.aligned.m16n8k16.row.col.f32.f16.f16.f32 "
        "{%0,%1,%2,%3}, {%4,%5,%6,%7}, {%8,%9}, {%0,%1,%2,%3};"
        : "+f"(d[0]), "+f"(d[1]), "+f"(d[2]), "+f"(d[3])
        : "r"(a0), "r"(a1), "r"(a2), "r"(a3), "r"(b0), "r"(b1));
}

// ---------------------------------------------------------------------------
// Split fp32 -> fp16 h0 + fp16 h1 (residual), pair-permuted per 16 k.
// One thread = 16 consecutive k of one row.
// ---------------------------------------------------------------------------
__global__ void split_kernel(const float* __restrict__ src, int ngroups, int which) {
    __half* d0 = which ? gBh0 : gAh0;
    __half* d1 = which ? gBh1 : gAh1;
    int g = blockIdx.x * blockDim.x + threadIdx.x;
    if (g >= ngroups) return;

    const float4* s4 = (const float4*)(src + (size_t)g * 16);
    float in[16];
    float4 x0 = s4[0], x1 = s4[1], x2 = s4[2], x3 = s4[3];
    in[0]=x0.x; in[1]=x0.y; in[2]=x0.z; in[3]=x0.w;
    in[4]=x1.x; in[5]=x1.y; in[6]=x1.z; in[7]=x1.w;
    in[8]=x2.x; in[9]=x2.y; in[10]=x2.z; in[11]=x2.w;
    in[12]=x3.x; in[13]=x3.y; in[14]=x3.z; in[15]=x3.w;

    __half h0[16], h1[16];
#pragma unroll
    for (int i = 0; i < 16; i++) {
        h0[i] = __float2half_rn(in[i]);
        h1[i] = __float2half_rn(in[i] - __half2float(h0[i]));
    }

    const int pp[8] = {0, 4, 1, 5, 2, 6, 3, 7};
    __half2 w0[8], w1[8];
#pragma unroll
    for (int j = 0; j < 8; j++) {
        int p = pp[j];
        w0[j] = __halves2half2(h0[2 * p], h0[2 * p + 1]);
        w1[j] = __halves2half2(h1[2 * p], h1[2 * p + 1]);
    }
    uint4* o0 = (uint4*)(d0 + (size_t)g * 16);
    uint4* o1 = (uint4*)(d1 + (size_t)g * 16);
    o0[0] = *(uint4*)&w0[0]; o0[1] = *(uint4*)&w0[4];
    o1[0] = *(uint4*)&w1[0]; o1[1] = *(uint4*)&w1[4];
}

// ---------------------------------------------------------------------------
// 10*||p_m||^2, one warp per row
// ---------------------------------------------------------------------------
__global__ void psq_kernel(const float* __restrict__ B) {
    int w = (blockIdx.x * blockDim.x + threadIdx.x) >> 5;
    int lane = threadIdx.x & 31;
    if (w >= M_PROTO) return;
    const float4* row = (const float4*)(B + (size_t)w * K_DIM);
    float s = 0.f;
#pragma unroll
    for (int i = 0; i < 4; i++) {
        float4 v = row[lane + i * 32];
        s += v.x * v.x + v.y * v.y + v.z * v.z + v.w * v.w;
    }
#pragma unroll
    for (int o = 16; o > 0; o >>= 1) s += __shfl_xor_sync(0xFFFFFFFFu, s, o);
    if (lane == 0) g_psq10[w] = 10.f * s;
}

// ---------------------------------------------------------------------------
// GEMM: S[n,m] = 20 * dot(feat_n, proto_m) - 10*||p_m||^2
// fp16 double-split emulation: cross = h0h0 + h0h1 + h1h0 (3 mma/tile/k16).
// CTA 128x128, BK=32 (16 iterations, 96 MMAs per barrier interval),
// 2-stage cp.async ring.
// Stage layout (words): Ah0[0,2048) Ah1[2048,4096) Bh0[4096,6144) Bh1[6144,8192)
// Tile rows: 32 fp16 = 16 words dense; 1-bit XOR swizzle flips the k16-group
// half for rows with bit1 set -> all frag-load and store phases conflict-free.
// word(row, g, q) = row*16 + ((g*8 + q*2) ^ ((row>>1 & 1) << 3))
// ---------------------------------------------------------------------------
#define STAGE_W   8192
#define STAGE_B   (STAGE_W * 4)
#define SMEM_TOT  (2 * STAGE_B)           // 65536 bytes
#define KT_STEPS  (K_DIM / 32)            // 16

__device__ __forceinline__ int wf(int row, int g, int q2) {
    // q2 = q*2 (word within 8-word group half)
    return row * 16 + ((g * 8 + q2) ^ ((row >> 1 & 1) << 3));
}

__global__ __launch_bounds__(256, 1)
void gemm_tc_kernel(float* __restrict__ S) {
    extern __shared__ float smem[];
    const uint32_t smem_base = smem_u32(smem);
    const int tid  = threadIdx.x;
    const int wid  = tid >> 5;
    const int lane = tid & 31;
    const int warpM = wid & 1;            // 2 warps in M (feat)
    const int warpN = wid >> 1;           // 4 warps in N (proto)
    const int m0 = blockIdx.x * 128;
    const int n0 = blockIdx.y * 128;

    float acc[4][4][4];
#pragma unroll
    for (int i = 0; i < 4; i++)
#pragma unroll
        for (int j = 0; j < 4; j++)
#pragma unroll
            for (int q = 0; q < 4; q++) acc[i][j][q] = 0.f;

    // ---- stage loader: 8 cp.async(16B) per thread (2048 chunks total) ----
    auto load_stage = [&](int buf, int kt) {
        uint32_t sb = smem_base + (uint32_t)buf * STAGE_B;
#pragma unroll
        for (int it = 0; it < 8; it++) {
            int chunk = tid + it * 256;
            int arr = chunk >> 9;                    // 0:Ah0 1:Ah1 2:Bh0 3:Bh1
            int cc  = chunk & 511;
            int row = cc >> 2, c = cc & 3;           // c = 16B chunk in row
            // dst word = arr*2048 + row*16 + (4c ^ swz(row))
            uint32_t dst = sb + (uint32_t)(arr * 2048 + row * 16 +
                                           ((4 * c) ^ ((row >> 1 & 1) << 3))) * 4u;
            const char* srcb;
            if (arr == 0)
                srcb = (const char*)gAh0 + ((size_t)(n0 + row) * K_DIM + kt * 32) * 2 + c * 16;
            else if (arr == 1)
                srcb = (const char*)gAh1 + ((size_t)(n0 + row) * K_DIM + kt * 32) * 2 + c * 16;
            else if (arr == 2)
                srcb = (const char*)gBh0 + ((size_t)(m0 + row) * K_DIM + kt * 32) * 2 + c * 16;
            else
                srcb = (const char*)gBh1 + ((size_t)(m0 + row) * K_DIM + kt * 32) * 2 + c * 16;
            CP_ASYNC16(dst, srcb);
        }
        CP_COMMIT();
    };

    load_stage(0, 0);
    load_stage(1, 1);

    const int r  = lane >> 2;
    const int q2 = (lane & 3) * 2;

    for (int kt = 0; kt < KT_STEPS; kt++) {
        const int b = kt & 1;
        CP_WAIT(1);
        __syncthreads();

        const float* st  = smem + b * STAGE_W;
        const float* sA0 = st;
        const float* sA1 = st + 2048;
        const float* sB0 = st + 4096;
        const float* sB1 = st + 6144;

#pragma unroll
        for (int g = 0; g < 2; g++) {               // two k16 groups in BK=32
            uint2 AH[4][2], AL[4][2], BH[4], BL[4];
#pragma unroll
            for (int nt = 0; nt < 4; nt++) {
                int col = warpN * 32 + nt * 8 + r;
                BH[nt] = *(const uint2*)(sB0 + wf(col, g, q2));
                BL[nt] = *(const uint2*)(sB1 + wf(col, g, q2));
            }
#pragma unroll
            for (int mt = 0; mt < 4; mt++) {
                int row = warpM * 64 + mt * 16 + r;
                AH[mt][0] = *(const uint2*)(sA0 + wf(row, g, q2));
                AH[mt][1] = *(const uint2*)(sA0 + wf(row + 8, g, q2));
                AL[mt][0] = *(const uint2*)(sA1 + wf(row, g, q2));
                AL[mt][1] = *(const uint2*)(sA1 + wf(row + 8, g, q2));
            }
#pragma unroll
            for (int mt = 0; mt < 4; mt++)
#pragma unroll
                for (int nt = 0; nt < 4; nt++) {
                    // h0*h0
                    mma_f16(acc[mt][nt],
                            AH[mt][0].x, AH[mt][1].x, AH[mt][0].y, AH[mt][1].y,
                            BH[nt].x, BH[nt].y);
                    // h0*h1
                    mma_f16(acc[mt][nt],
                            AH[mt][0].x, AH[mt][1].x, AH[mt][0].y, AH[mt][1].y,
                            BL[nt].x, BL[nt].y);
                    // h1*h0
                    mma_f16(acc[mt][nt],
                            AL[mt][0].x, AL[mt][1].x, AL[mt][0].y, AL[mt][1].y,
                            BH[nt].x, BH[nt].y);
                }
        }

        __syncthreads();
        if (kt + 2 < KT_STEPS) load_stage(b, kt + 2);
    }

    // ---- epilogue ----
    float* sp = smem;
    __syncthreads();
    if (tid < 128) sp[tid] = g_psq10[m0 + tid];
    __syncthreads();

#pragma unroll
    for (int mt = 0; mt < 4; mt++) {
        int gr = n0 + warpM * 64 + mt * 16 + r;
#pragma unroll
        for (int nt = 0; nt < 4; nt++) {
            int lc = warpN * 32 + nt * 8 + q2;
            float p0 = sp[lc], p1 = sp[lc + 1];
            float2 o0, o1;
            o0.x = 20.f * acc[mt][nt][0] - p0;
            o0.y = 20.f * acc[mt][nt][1] - p1;
            o1.x = 20.f * acc[mt][nt][2] - p0;
            o1.y = 20.f * acc[mt][nt][3] - p1;
            *(float2*)(S + (size_t)gr * M_PROTO + m0 + lc) = o0;
            *(float2*)(S + (size_t)(gr + 8) * M_PROTO + m0 + lc) = o1;
        }
    }
}

// ---------------------------------------------------------------------------
// Row softmax (in place), quality = 1/sum(exp), max_id = first argmax
// ---------------------------------------------------------------------------
__global__ void softmax_kernel(float* __restrict__ S,
                               float* __restrict__ quality,
                               float* __restrict__ maxid) {
    const int row = blockIdx.x;
    float* srow = S + (size_t)row * M_PROTO;
    const int t = threadIdx.x;

    float v[8];
    float4 v0 = *(const float4*)(srow + t * 8 + 0);
    float4 v1 = *(const float4*)(srow + t * 8 + 4);
    v[0] = v0.x; v[1] = v0.y; v[2] = v0.z; v[3] = v0.w;
    v[4] = v1.x; v[5] = v1.y; v[6] = v1.z; v[7] = v1.w;

    float lmax = v[0];
    int   limx = t * 8;
#pragma unroll
    for (int j = 1; j < 8; j++)
        if (v[j] > lmax) { lmax = v[j]; limx = t * 8 + j; }

    __shared__ float smax[256];
    __shared__ int   sidx[256];
    smax[t] = lmax;
    sidx[t] = limx;
    __syncthreads();
#pragma unroll
    for (int s = 128; s > 0; s >>= 1) {
        if (t < s) {
            float v2 = smax[t + s];
            int   i2 = sidx[t + s];
            if (v2 > smax[t] || (v2 == smax[t] && i2 < sidx[t])) {
                smax[t] = v2; sidx[t] = i2;
            }
        }
        __syncthreads();
    }
    const float rowmax = smax[0];
    const int   rowarg = sidx[0];
    __syncthreads();

    float e[8];
    float lsum = 0.f;
#pragma unroll
    for (int j = 0; j < 8; j++) { e[j] = expf(v[j] - rowmax); lsum += e[j]; }
    smax[t] = lsum;
    __syncthreads();
#pragma unroll
    for (int s = 128; s > 0; s >>= 1) {
        if (t < s) smax[t] += smax[t + s];
        __syncthreads();
    }
    const float inv = 1.0f / smax[0];

    float4 o0, o1;
    o0.x = e[0] * inv; o0.y = e[1] * inv; o0.z = e[2] * inv; o0.w = e[3] * inv;
    o1.x = e[4] * inv; o1.y = e[5] * inv; o1.z = e[6] * inv; o1.w = e[7] * inv;
    *(float4*)(srow + t * 8 + 0) = o0;
    *(float4*)(srow + t * 8 + 4) = o1;

    if (t == 0) {
        quality[row] = inv;
        maxid[row]   = (float)rowarg;
    }
}

// ---------------------------------------------------------------------------
extern "C" void kernel_launch(void* const* d_in, const int* in_sizes, int n_in,
                              void* d_out, int out_size) {
    const float* feat  = (const float*)d_in[0];   // [32768, 512]
    const float* proto = (const float*)d_in[1];   // [2048, 512]
    float* out = (float*)d_out;

    float* quality = out;
    float* maxid   = out + N_FEAT;
    float* pred    = out + 2 * N_FEAT;

    cudaFuncSetAttribute(gemm_tc_kernel,
                         cudaFuncAttributeMaxDynamicSharedMemorySize, SMEM_TOT);

    int gA = N_FEAT * K_DIM / 16;
    int gB = M_PROTO * K_DIM / 16;
    split_kernel<<<(gA + 255) / 256, 256>>>(feat, gA, 0);
    split_kernel<<<(gB + 255) / 256, 256>>>(proto, gB, 1);
    psq_kernel<<<M_PROTO / 8, 256>>>(proto);

    dim3 grid(M_PROTO / 128, N_FEAT / 128);
    gemm_tc_kernel<<<grid, 256, SMEM_TOT>>>(pred);

    softmax_kernel<<<N_FEAT, 256>>>(pred, quality, maxid);
}

// round 12
// speedup vs baseline: 1.7694x; 1.1326x over previous
#include <cuda_runtime.h>
#include <cuda_fp16.h>
#include <math.h>
#include <stdint.h>

// Problem shape (fixed by setup_inputs)
#define N_FEAT  32768
#define M_PROTO 2048
#define K_DIM   512

// ---------------------------------------------------------------------------
// Static device scratch (no cudaMalloc allowed)
// fp16 double-split (x = h0 + h1), pair-permuted per 16-k group:
// phys pair slot j holds logical pair pp[j], pp = {0,4,1,5,2,6,3,7}
// => 8B unit q = logical pairs (q, q+4) = exactly one mma fragment (a0,a2)
// ---------------------------------------------------------------------------
__device__ __half gAh0[(size_t)N_FEAT * K_DIM];
__device__ __half gAh1[(size_t)N_FEAT * K_DIM];
__device__ __half gBh0[(size_t)M_PROTO * K_DIM];
__device__ __half gBh1[(size_t)M_PROTO * K_DIM];
__device__ float g_psq10[M_PROTO];      // 10 * ||p_m||^2

// ---------------------------------------------------------------------------
__device__ __forceinline__ uint32_t smem_u32(const void* p) {
    uint32_t a;
    asm("{ .reg .u64 t; cvta.to.shared.u64 t, %1; cvt.u32.u64 %0, t; }" : "=r"(a) : "l"(p));
    return a;
}
#define CP_ASYNC16(dst, src) \
    asm volatile("cp.async.cg.shared.global [%0], [%1], 16;" :: "r"(dst), "l"(src) : "memory")
#define CP_COMMIT() asm volatile("cp.async.commit_group;" ::: "memory")
#define CP_WAIT(n)  asm volatile("cp.async.wait_group %0;" :: "n"(n) : "memory")

// mma.sync m16n8k16 fp16 with fp32 accumulate (sm_80 baseline)
__device__ __forceinline__ void mma_f16(float* d,
                                        uint32_t a0, uint32_t a1, uint32_t a2, uint32_t a3,
                                        uint32_t b0, uint32_t b1) {
    asm volatile(
        "mma.sync.aligned.m16n8k16.row.col.f32.f16.f16.f32 "
        "{%0,%1,%2,%3}, {%4,%5,%6,%7}, {%8,%9}, {%0,%1,%2,%3};"
        : "+f"(d[0]), "+f"(d[1]), "+f"(d[2]), "+f"(d[3])
        : "r"(a0), "r"(a1), "r"(a2), "r"(a3), "r"(b0), "r"(b1));
}

// ---------------------------------------------------------------------------
// Split fp32 -> fp16 h0 + fp16 h1 (residual), pair-permuted per 16 k.
// One thread = 16 consecutive k of one row.
// ---------------------------------------------------------------------------
__global__ void split_kernel(const float* __restrict__ src, int ngroups, int which) {
    __half* d0 = which ? gBh0 : gAh0;
    __half* d1 = which ? gBh1 : gAh1;
    int g = blockIdx.x * blockDim.x + threadIdx.x;
    if (g >= ngroups) return;

    const float4* s4 = (const float4*)(src + (size_t)g * 16);
    float in[16];
    float4 x0 = s4[0], x1 = s4[1], x2 = s4[2], x3 = s4[3];
    in[0]=x0.x; in[1]=x0.y; in[2]=x0.z; in[3]=x0.w;
    in[4]=x1.x; in[5]=x1.y; in[6]=x1.z; in[7]=x1.w;
    in[8]=x2.x; in[9]=x2.y; in[10]=x2.z; in[11]=x2.w;
    in[12]=x3.x; in[13]=x3.y; in[14]=x3.z; in[15]=x3.w;

    __half h0[16], h1[16];
#pragma unroll
    for (int i = 0; i < 16; i++) {
        h0[i] = __float2half_rn(in[i]);
        h1[i] = __float2half_rn(in[i] - __half2float(h0[i]));
    }

    const int pp[8] = {0, 4, 1, 5, 2, 6, 3, 7};
    __half2 w0[8], w1[8];
#pragma unroll
    for (int j = 0; j < 8; j++) {
        int p = pp[j];
        w0[j] = __halves2half2(h0[2 * p], h0[2 * p + 1]);
        w1[j] = __halves2half2(h1[2 * p], h1[2 * p + 1]);
    }
    uint4* o0 = (uint4*)(d0 + (size_t)g * 16);
    uint4* o1 = (uint4*)(d1 + (size_t)g * 16);
    o0[0] = *(uint4*)&w0[0]; o0[1] = *(uint4*)&w0[4];
    o1[0] = *(uint4*)&w1[0]; o1[1] = *(uint4*)&w1[4];
}

// ---------------------------------------------------------------------------
// 10*||p_m||^2, one warp per row
// ---------------------------------------------------------------------------
__global__ void psq_kernel(const float* __restrict__ B) {
    int w = (blockIdx.x * blockDim.x + threadIdx.x) >> 5;
    int lane = threadIdx.x & 31;
    if (w >= M_PROTO) return;
    const float4* row = (const float4*)(B + (size_t)w * K_DIM);
    float s = 0.f;
#pragma unroll
    for (int i = 0; i < 4; i++) {
        float4 v = row[lane + i * 32];
        s += v.x * v.x + v.y * v.y + v.z * v.z + v.w * v.w;
    }
#pragma unroll
    for (int o = 16; o > 0; o >>= 1) s += __shfl_xor_sync(0xFFFFFFFFu, s, o);
    if (lane == 0) g_psq10[w] = 10.f * s;
}

// ---------------------------------------------------------------------------
// GEMM: S[n,m] = 20 * dot(feat_n, proto_m) - 10*||p_m||^2
// fp16 double-split emulation: cross = h0h0 + h0h1 + h1h0 (3 mma/tile/k16).
// CTA 128x128, BK=64 (8 iterations, 192 MMAs per barrier interval),
// 2-stage cp.async ring.
// Stage layout (words): Ah0[0,4096) Ah1[4096,8192) Bh0[8192,12288) Bh1[12288,16384)
// Tile rows: 64 fp16 = 32 words; 2-bit XOR swizzle on word bits 3-4:
//   swz(row) = ((row&1)<<4) | (((row>>1)&1)<<3)
//   word(row, g, q2) = row*32 + ((g*8 + q2) ^ swz(row))
// Enumerated conflict-free for fragment LDS.64 phases and STS.128 store phases;
// low 3 bits untouched -> pair-permuted (q,q+4) LDS.64 fragments preserved.
// ---------------------------------------------------------------------------
#define STAGE_W   16384
#define STAGE_B   (STAGE_W * 4)
#define SMEM_TOT  (2 * STAGE_B)           // 131072 bytes
#define KT_STEPS  (K_DIM / 64)            // 8

__device__ __forceinline__ int swzr(int row) {
    return ((row & 1) << 4) | (((row >> 1) & 1) << 3);
}
__device__ __forceinline__ int wf(int row, int g, int q2) {
    return row * 32 + ((g * 8 + q2) ^ swzr(row));
}

__global__ __launch_bounds__(256, 1)
void gemm_tc_kernel(float* __restrict__ S) {
    extern __shared__ float smem[];
    const uint32_t smem_base = smem_u32(smem);
    const int tid  = threadIdx.x;
    const int wid  = tid >> 5;
    const int lane = tid & 31;
    const int warpM = wid & 1;            // 2 warps in M (feat)
    const int warpN = wid >> 1;           // 4 warps in N (proto)
    const int m0 = blockIdx.x * 128;
    const int n0 = blockIdx.y * 128;

    float acc[4][4][4];
#pragma unroll
    for (int i = 0; i < 4; i++)
#pragma unroll
        for (int j = 0; j < 4; j++)
#pragma unroll
            for (int q = 0; q < 4; q++) acc[i][j][q] = 0.f;

    // ---- stage loader: 16 cp.async(16B) per thread (4096 chunks total) ----
    auto load_stage = [&](int buf, int kt) {
        uint32_t sb = smem_base + (uint32_t)buf * STAGE_B;
#pragma unroll
        for (int it = 0; it < 16; it++) {
            int chunk = tid + it * 256;
            int arr = chunk >> 10;                   // 0:Ah0 1:Ah1 2:Bh0 3:Bh1
            int cc  = chunk & 1023;
            int row = cc >> 3, c = cc & 7;           // c = 16B chunk in 128B row
            uint32_t dst = sb + (uint32_t)(arr * 4096 + row * 32 +
                                           ((4 * c) ^ swzr(row))) * 4u;
            const char* srcb;
            if (arr == 0)
                srcb = (const char*)gAh0 + ((size_t)(n0 + row) * K_DIM + kt * 64) * 2 + c * 16;
            else if (arr == 1)
                srcb = (const char*)gAh1 + ((size_t)(n0 + row) * K_DIM + kt * 64) * 2 + c * 16;
            else if (arr == 2)
                srcb = (const char*)gBh0 + ((size_t)(m0 + row) * K_DIM + kt * 64) * 2 + c * 16;
            else
                srcb = (const char*)gBh1 + ((size_t)(m0 + row) * K_DIM + kt * 64) * 2 + c * 16;
            CP_ASYNC16(dst, srcb);
        }
        CP_COMMIT();
    };

    load_stage(0, 0);
    load_stage(1, 1);

    const int r  = lane >> 2;
    const int q2 = (lane & 3) * 2;

    for (int kt = 0; kt < KT_STEPS; kt++) {
        const int b = kt & 1;
        CP_WAIT(1);
        __syncthreads();

        const float* st  = smem + b * STAGE_W;
        const float* sA0 = st;
        const float* sA1 = st + 4096;
        const float* sB0 = st + 8192;
        const float* sB1 = st + 12288;

#pragma unroll
        for (int g = 0; g < 4; g++) {               // four k16 groups in BK=64
            uint2 AH[4][2], AL[4][2], BH[4], BL[4];
#pragma unroll
            for (int nt = 0; nt < 4; nt++) {
                int col = warpN * 32 + nt * 8 + r;
                BH[nt] = *(const uint2*)(sB0 + wf(col, g, q2));
                BL[nt] = *(const uint2*)(sB1 + wf(col, g, q2));
            }
#pragma unroll
            for (int mt = 0; mt < 4; mt++) {
                int row = warpM * 64 + mt * 16 + r;
                AH[mt][0] = *(const uint2*)(sA0 + wf(row, g, q2));
                AH[mt][1] = *(const uint2*)(sA0 + wf(row + 8, g, q2));
                AL[mt][0] = *(const uint2*)(sA1 + wf(row, g, q2));
                AL[mt][1] = *(const uint2*)(sA1 + wf(row + 8, g, q2));
            }
#pragma unroll
            for (int mt = 0; mt < 4; mt++)
#pragma unroll
                for (int nt = 0; nt < 4; nt++) {
                    // h0*h0
                    mma_f16(acc[mt][nt],
                            AH[mt][0].x, AH[mt][1].x, AH[mt][0].y, AH[mt][1].y,
                            BH[nt].x, BH[nt].y);
                    // h0*h1
                    mma_f16(acc[mt][nt],
                            AH[mt][0].x, AH[mt][1].x, AH[mt][0].y, AH[mt][1].y,
                            BL[nt].x, BL[nt].y);
                    // h1*h0
                    mma_f16(acc[mt][nt],
                            AL[mt][0].x, AL[mt][1].x, AL[mt][0].y, AL[mt][1].y,
                            BH[nt].x, BH[nt].y);
                }
        }

        __syncthreads();
        if (kt + 2 < KT_STEPS) load_stage(b, kt + 2);
    }

    // ---- epilogue ----
    float* sp = smem;
    __syncthreads();
    if (tid < 128) sp[tid] = g_psq10[m0 + tid];
    __syncthreads();

#pragma unroll
    for (int mt = 0; mt < 4; mt++) {
        int gr = n0 + warpM * 64 + mt * 16 + r;
#pragma unroll
        for (int nt = 0; nt < 4; nt++) {
            int lc = warpN * 32 + nt * 8 + q2;
            float p0 = sp[lc], p1 = sp[lc + 1];
            float2 o0, o1;
            o0.x = 20.f * acc[mt][nt][0] - p0;
            o0.y = 20.f * acc[mt][nt][1] - p1;
            o1.x = 20.f * acc[mt][nt][2] - p0;
            o1.y = 20.f * acc[mt][nt][3] - p1;
            *(float2*)(S + (size_t)gr * M_PROTO + m0 + lc) = o0;
            *(float2*)(S + (size_t)(gr + 8) * M_PROTO + m0 + lc) = o1;
        }
    }
}

// ---------------------------------------------------------------------------
// Row softmax (in place), quality = 1/sum(exp), max_id = first argmax
// ---------------------------------------------------------------------------
__global__ void softmax_kernel(float* __restrict__ S,
                               float* __restrict__ quality,
                               float* __restrict__ maxid) {
    const int row = blockIdx.x;
    float* srow = S + (size_t)row * M_PROTO;
    const int t = threadIdx.x;

    float v[8];
    float4 v0 = *(const float4*)(srow + t * 8 + 0);
    float4 v1 = *(const float4*)(srow + t * 8 + 4);
    v[0] = v0.x; v[1] = v0.y; v[2] = v0.z; v[3] = v0.w;
    v[4] = v1.x; v[5] = v1.y; v[6] = v1.z; v[7] = v1.w;

    float lmax = v[0];
    int   limx = t * 8;
#pragma unroll
    for (int j = 1; j < 8; j++)
        if (v[j] > lmax) { lmax = v[j]; limx = t * 8 + j; }

    __shared__ float smax[256];
    __shared__ int   sidx[256];
    smax[t] = lmax;
    sidx[t] = limx;
    __syncthreads();
#pragma unroll
    for (int s = 128; s > 0; s >>= 1) {
        if (t < s) {
            float v2 = smax[t + s];
            int   i2 = sidx[t + s];
            if (v2 > smax[t] || (v2 == smax[t] && i2 < sidx[t])) {
                smax[t] = v2; sidx[t] = i2;
            }
        }
        __syncthreads();
    }
    const float rowmax = smax[0];
    const int   rowarg = sidx[0];
    __syncthreads();

    float e[8];
    float lsum = 0.f;
#pragma unroll
    for (int j = 0; j < 8; j++) { e[j] = expf(v[j] - rowmax); lsum += e[j]; }
    smax[t] = lsum;
    __syncthreads();
#pragma unroll
    for (int s = 128; s > 0; s >>= 1) {
        if (t < s) smax[t] += smax[t + s];
        __syncthreads();
    }
    const float inv = 1.0f / smax[0];

    float4 o0, o1;
    o0.x = e[0] * inv; o0.y = e[1] * inv; o0.z = e[2] * inv; o0.w = e[3] * inv;
    o1.x = e[4] * inv; o1.y = e[5] * inv; o1.z = e[6] * inv; o1.w = e[7] * inv;
    *(float4*)(srow + t * 8 + 0) = o0;
    *(float4*)(srow + t * 8 + 4) = o1;

    if (t == 0) {
        quality[row] = inv;
        maxid[row]   = (float)rowarg;
    }
}

// ---------------------------------------------------------------------------
extern "C" void kernel_launch(void* const* d_in, const int* in_sizes, int n_in,
                              void* d_out, int out_size) {
    const float* feat  = (const float*)d_in[0];   // [32768, 512]
    const float* proto = (const float*)d_in[1];   // [2048, 512]
    float* out = (float*)d_out;

    float* quality = out;
    float* maxid   = out + N_FEAT;
    float* pred    = out + 2 * N_FEAT;

    cudaFuncSetAttribute(gemm_tc_kernel,
                         cudaFuncAttributeMaxDynamicSharedMemorySize, SMEM_TOT);

    int gA = N_FEAT * K_DIM / 16;
    int gB = M_PROTO * K_DIM / 16;
    split_kernel<<<(gA + 255) / 256, 256>>>(feat, gA, 0);
    split_kernel<<<(gB + 255) / 256, 256>>>(proto, gB, 1);
    psq_kernel<<<M_PROTO / 8, 256>>>(proto);

    dim3 grid(M_PROTO / 128, N_FEAT / 128);
    gemm_tc_kernel<<<grid, 256, SMEM_TOT>>>(pred);

    softmax_kernel<<<N_FEAT, 256>>>(pred, quality, maxid);
}

// round 15
// speedup vs baseline: 1.9147x; 1.0821x over previous
#include <cuda_runtime.h>
#include <cuda_fp16.h>
#include <math.h>
#include <stdint.h>

// Problem shape (fixed by setup_inputs)
#define N_FEAT  32768
#define M_PROTO 2048
#define K_DIM   512

// ---------------------------------------------------------------------------
// Static device scratch (no cudaMalloc allowed)
// fp16 double-split (x = h0 + h1), pair-permuted per 16-k group:
// phys pair slot j holds logical pair pp[j], pp = {0,4,1,5,2,6,3,7}
// => 8B unit q = logical pairs (q, q+4) = exactly one mma fragment (a0,a2)
// ---------------------------------------------------------------------------
__device__ __half gAh0[(size_t)N_FEAT * K_DIM];
__device__ __half gAh1[(size_t)N_FEAT * K_DIM];
__device__ __half gBh0[(size_t)M_PROTO * K_DIM];
__device__ __half gBh1[(size_t)M_PROTO * K_DIM];
__device__ float g_psq10[M_PROTO];      // 10 * ||p_m||^2

// ---------------------------------------------------------------------------
__device__ __forceinline__ uint32_t smem_u32(const void* p) {
    uint32_t a;
    asm("{ .reg .u64 t; cvta.to.shared.u64 t, %1; cvt.u32.u64 %0, t; }" : "=r"(a) : "l"(p));
    return a;
}
#define CP_ASYNC16(dst, src) \
    asm volatile("cp.async.cg.shared.global [%0], [%1], 16;" :: "r"(dst), "l"(src) : "memory")
#define CP_COMMIT() asm volatile("cp.async.commit_group;" ::: "memory")
#define CP_WAIT(n)  asm volatile("cp.async.wait_group %0;" :: "n"(n) : "memory")

// mma.sync m16n8k16 fp16 with fp32 accumulate (sm_80 baseline)
__device__ __forceinline__ void mma_f16(float* d,
                                        uint32_t a0, uint32_t a1, uint32_t a2, uint32_t a3,
                                        uint32_t b0, uint32_t b1) {
    asm volatile(
        "mma.sync.aligned.m16n8k16.row.col.f32.f16.f16.f32 "
        "{%0,%1,%2,%3}, {%4,%5,%6,%7}, {%8,%9}, {%0,%1,%2,%3};"
        : "+f"(d[0]), "+f"(d[1]), "+f"(d[2]), "+f"(d[3])
        : "r"(a0), "r"(a1), "r"(a2), "r"(a3), "r"(b0), "r"(b1));
}

// ---------------------------------------------------------------------------
// Split fp32 -> fp16 h0 + fp16 h1 (residual), pair-permuted per 16 k.
// One thread = 16 consecutive k of one row.
// ---------------------------------------------------------------------------
__global__ void split_kernel(const float* __restrict__ src, int ngroups, int which) {
    __half* d0 = which ? gBh0 : gAh0;
    __half* d1 = which ? gBh1 : gAh1;
    int g = blockIdx.x * blockDim.x + threadIdx.x;
    if (g >= ngroups) return;

    const float4* s4 = (const float4*)(src + (size_t)g * 16);
    float in[16];
    float4 x0 = s4[0], x1 = s4[1], x2 = s4[2], x3 = s4[3];
    in[0]=x0.x; in[1]=x0.y; in[2]=x0.z; in[3]=x0.w;
    in[4]=x1.x; in[5]=x1.y; in[6]=x1.z; in[7]=x1.w;
    in[8]=x2.x; in[9]=x2.y; in[10]=x2.z; in[11]=x2.w;
    in[12]=x3.x; in[13]=x3.y; in[14]=x3.z; in[15]=x3.w;

    __half h0[16], h1[16];
#pragma unroll
    for (int i = 0; i < 16; i++) {
        h0[i] = __float2half_rn(in[i]);
        h1[i] = __float2half_rn(in[i] - __half2float(h0[i]));
    }

    const int pp[8] = {0, 4, 1, 5, 2, 6, 3, 7};
    __half2 w0[8], w1[8];
#pragma unroll
    for (int j = 0; j < 8; j++) {
        int p = pp[j];
        w0[j] = __halves2half2(h0[2 * p], h0[2 * p + 1]);
        w1[j] = __halves2half2(h1[2 * p], h1[2 * p + 1]);
    }
    uint4* o0 = (uint4*)(d0 + (size_t)g * 16);
    uint4* o1 = (uint4*)(d1 + (size_t)g * 16);
    o0[0] = *(uint4*)&w0[0]; o0[1] = *(uint4*)&w0[4];
    o1[0] = *(uint4*)&w1[0]; o1[1] = *(uint4*)&w1[4];
}

// ---------------------------------------------------------------------------
// 10*||p_m||^2, one warp per row
// ---------------------------------------------------------------------------
__global__ void psq_kernel(const float* __restrict__ B) {
    int w = (blockIdx.x * blockDim.x + threadIdx.x) >> 5;
    int lane = threadIdx.x & 31;
    if (w >= M_PROTO) return;
    const float4* row = (const float4*)(B + (size_t)w * K_DIM);
    float s = 0.f;
#pragma unroll
    for (int i = 0; i < 4; i++) {
        float4 v = row[lane + i * 32];
        s += v.x * v.x + v.y * v.y + v.z * v.z + v.w * v.w;
    }
#pragma unroll
    for (int o = 16; o > 0; o >>= 1) s += __shfl_xor_sync(0xFFFFFFFFu, s, o);
    if (lane == 0) g_psq10[w] = 10.f * s;
}

// ---------------------------------------------------------------------------
// GEMM: S[n,m] = 20 * dot(feat_n, proto_m) - 10*||p_m||^2
// fp16 double-split emulation: cross = h0h0 + h0h1 + h1h0 (3 mma/tile/k16).
// CTA tile 128 (feat) x 256 (proto), warp tile 64x64 (2M x 4N warps),
// BK=64 (8 iterations, 384 MMAs per barrier interval), 2-stage cp.async ring.
// Stage layout (words): Ah0[0,4096) Ah1[4096,8192) Bh0[8192,16384) Bh1[16384,24576)
// Rows: 64 fp16 = 32 words; 2-bit XOR swizzle on word bits 3-4 (as R12,
// enumerated conflict-free for frag LDS.64 and 16B store phases).
// ---------------------------------------------------------------------------
#define STAGE_W   24576
#define STAGE_B   (STAGE_W * 4)
#define SMEM_TOT  (2 * STAGE_B)           // 196608 bytes
#define KT_STEPS  (K_DIM / 64)            // 8

__device__ __forceinline__ int swzr(int row) {
    return ((row & 1) << 4) | (((row >> 1) & 1) << 3);
}
__device__ __forceinline__ int wf(int row, int g, int q2) {
    return row * 32 + ((g * 8 + q2) ^ swzr(row));
}

__global__ __launch_bounds__(256, 1)
void gemm_tc_kernel(float* __restrict__ S) {
    extern __shared__ float smem[];
    const uint32_t smem_base = smem_u32(smem);
    const int tid  = threadIdx.x;
    const int wid  = tid >> 5;
    const int lane = tid & 31;
    const int warpM = wid & 1;            // 2 warps in M (feat), 64 rows each
    const int warpN = wid >> 1;           // 4 warps in N (proto), 64 cols each
    const int m0 = blockIdx.x * 256;
    const int n0 = blockIdx.y * 128;

    float acc[4][8][4];
#pragma unroll
    for (int i = 0; i < 4; i++)
#pragma unroll
        for (int j = 0; j < 8; j++)
#pragma unroll
            for (int q = 0; q < 4; q++) acc[i][j][q] = 0.f;

    // ---- stage loader: 24 cp.async(16B) per thread (6144 chunks total) ----
    // chunks: [0,1024) Ah0 | [1024,2048) Ah1 | [2048,4096) Bh0 | [4096,6144) Bh1
    auto load_stage = [&](int buf, int kt) {
        uint32_t sb = smem_base + (uint32_t)buf * STAGE_B;
#pragma unroll
        for (int it = 0; it < 24; it++) {
            int chunk = tid + it * 256;
            const char* srcb;
            uint32_t dst;
            if (it < 8) {                            // A tiles: 2048 chunks
                int arr = chunk >> 10;               // 0:Ah0 1:Ah1
                int cc  = chunk & 1023;
                int row = cc >> 3, c = cc & 7;
                dst = sb + (uint32_t)(arr * 4096 + row * 32 +
                                      ((4 * c) ^ swzr(row))) * 4u;
                const __half* gsrc = arr ? gAh1 : gAh0;
                srcb = (const char*)gsrc + ((size_t)(n0 + row) * K_DIM + kt * 64) * 2 + c * 16;
            } else {                                 // B tiles: 4096 chunks
                int idx = chunk - 2048;
                int arr = idx >> 11;                 // 0:Bh0 1:Bh1
                int cc  = idx & 2047;
                int row = cc >> 3, c = cc & 7;       // row 0..255
                dst = sb + (uint32_t)(8192 + arr * 8192 + row * 32 +
                                      ((4 * c) ^ swzr(row))) * 4u;
                const __half* gsrc = arr ? gBh1 : gBh0;
                srcb = (const char*)gsrc + ((size_t)(m0 + row) * K_DIM + kt * 64) * 2 + c * 16;
            }
            CP_ASYNC16(dst, srcb);
        }
        CP_COMMIT();
    };

    load_stage(0, 0);
    load_stage(1, 1);

    const int r  = lane >> 2;
    const int q2 = (lane & 3) * 2;

    for (int kt = 0; kt < KT_STEPS; kt++) {
        const int b = kt & 1;
        CP_WAIT(1);
        __syncthreads();

        const float* st  = smem + b * STAGE_W;
        const float* sA0 = st;
        const float* sA1 = st + 4096;
        const float* sB0 = st + 8192;
        const float* sB1 = st + 16384;

#pragma unroll
        for (int g = 0; g < 4; g++) {               // four k16 groups in BK=64
            uint2 BH[8], BL[8];
#pragma unroll
            for (int nt = 0; nt < 8; nt++) {
                int col = warpN * 64 + nt * 8 + r;
                BH[nt] = *(const uint2*)(sB0 + wf(col, g, q2));
                BL[nt] = *(const uint2*)(sB1 + wf(col, g, q2));
            }
#pragma unroll
            for (int mt = 0; mt < 4; mt++) {
                int row = warpM * 64 + mt * 16 + r;
                uint2 ah0 = *(const uint2*)(sA0 + wf(row, g, q2));
                uint2 ah1 = *(const uint2*)(sA0 + wf(row + 8, g, q2));
                uint2 al0 = *(const uint2*)(sA1 + wf(row, g, q2));
                uint2 al1 = *(const uint2*)(sA1 + wf(row + 8, g, q2));
#pragma unroll
                for (int nt = 0; nt < 8; nt++) {
                    // h0*h0
                    mma_f16(acc[mt][nt], ah0.x, ah1.x, ah0.y, ah1.y,
                            BH[nt].x, BH[nt].y);
                    // h0*h1
                    mma_f16(acc[mt][nt], ah0.x, ah1.x, ah0.y, ah1.y,
                            BL[nt].x, BL[nt].y);
                    // h1*h0
                    mma_f16(acc[mt][nt], al0.x, al1.x, al0.y, al1.y,
                            BH[nt].x, BH[nt].y);
                }
            }
        }

        __syncthreads();
        if (kt + 2 < KT_STEPS) load_stage(b, kt + 2);
    }

    // ---- epilogue ----
    float* sp = smem;
    __syncthreads();
    sp[tid] = g_psq10[m0 + tid];        // 256 threads load 256 psq values
    __syncthreads();

#pragma unroll
    for (int mt = 0; mt < 4; mt++) {
        int gr = n0 + warpM * 64 + mt * 16 + r;
#pragma unroll
        for (int nt = 0; nt < 8; nt++) {
            int lc = warpN * 64 + nt * 8 + q2;
            float p0 = sp[lc], p1 = sp[lc + 1];
            float2 o0, o1;
            o0.x = 20.f * acc[mt][nt][0] - p0;
            o0.y = 20.f * acc[mt][nt][1] - p1;
            o1.x = 20.f * acc[mt][nt][2] - p0;
            o1.y = 20.f * acc[mt][nt][3] - p1;
            *(float2*)(S + (size_t)gr * M_PROTO + m0 + lc) = o0;
            *(float2*)(S + (size_t)(gr + 8) * M_PROTO + m0 + lc) = o1;
        }
    }
}

// ---------------------------------------------------------------------------
// Row softmax (in place), quality = 1/sum(exp), max_id = first argmax
// ---------------------------------------------------------------------------
__global__ void softmax_kernel(float* __restrict__ S,
                               float* __restrict__ quality,
                               float* __restrict__ maxid) {
    const int row = blockIdx.x;
    float* srow = S + (size_t)row * M_PROTO;
    const int t = threadIdx.x;

    float v[8];
    float4 v0 = *(const float4*)(srow + t * 8 + 0);
    float4 v1 = *(const float4*)(srow + t * 8 + 4);
    v[0] = v0.x; v[1] = v0.y; v[2] = v0.z; v[3] = v0.w;
    v[4] = v1.x; v[5] = v1.y; v[6] = v1.z; v[7] = v1.w;

    float lmax = v[0];
    int   limx = t * 8;
#pragma unroll
    for (int j = 1; j < 8; j++)
        if (v[j] > lmax) { lmax = v[j]; limx = t * 8 + j; }

    __shared__ float smax[256];
    __shared__ int   sidx[256];
    smax[t] = lmax;
    sidx[t] = limx;
    __syncthreads();
#pragma unroll
    for (int s = 128; s > 0; s >>= 1) {
        if (t < s) {
            float v2 = smax[t + s];
            int   i2 = sidx[t + s];
            if (v2 > smax[t] || (v2 == smax[t] && i2 < sidx[t])) {
                smax[t] = v2; sidx[t] = i2;
            }
        }
        __syncthreads();
    }
    const float rowmax = smax[0];
    const int   rowarg = sidx[0];
    __syncthreads();

    float e[8];
    float lsum = 0.f;
#pragma unroll
    for (int j = 0; j < 8; j++) { e[j] = expf(v[j] - rowmax); lsum += e[j]; }
    smax[t] = lsum;
    __syncthreads();
#pragma unroll
    for (int s = 128; s > 0; s >>= 1) {
        if (t < s) smax[t] += smax[t + s];
        __syncthreads();
    }
    const float inv = 1.0f / smax[0];

    float4 o0, o1;
    o0.x = e[0] * inv; o0.y = e[1] * inv; o0.z = e[2] * inv; o0.w = e[3] * inv;
    o1.x = e[4] * inv; o1.y = e[5] * inv; o1.z = e[6] * inv; o1.w = e[7] * inv;
    *(float4*)(srow + t * 8 + 0) = o0;
    *(float4*)(srow + t * 8 + 4) = o1;

    if (t == 0) {
        quality[row] = inv;
        maxid[row]   = (float)rowarg;
    }
}

// ---------------------------------------------------------------------------
extern "C" void kernel_launch(void* const* d_in, const int* in_sizes, int n_in,
                              void* d_out, int out_size) {
    const float* feat  = (const float*)d_in[0];   // [32768, 512]
    const float* proto = (const float*)d_in[1];   // [2048, 512]
    float* out = (float*)d_out;

    float* quality = out;
    float* maxid   = out + N_FEAT;
    float* pred    = out + 2 * N_FEAT;

    cudaFuncSetAttribute(gemm_tc_kernel,
                         cudaFuncAttributeMaxDynamicSharedMemorySize, SMEM_TOT);

    int gA = N_FEAT * K_DIM / 16;
    int gB = M_PROTO * K_DIM / 16;
    split_kernel<<<(gA + 255) / 256, 256>>>(feat, gA, 0);
    split_kernel<<<(gB + 255) / 256, 256>>>(proto, gB, 1);
    psq_kernel<<<M_PROTO / 8, 256>>>(proto);

    dim3 grid(M_PROTO / 256, N_FEAT / 128);
    gemm_tc_kernel<<<grid, 256, SMEM_TOT>>>(pred);

    softmax_kernel<<<N_FEAT, 256>>>(pred, quality, maxid);
}

// round 16
// speedup vs baseline: 1.9885x; 1.0385x over previous
#include <cuda_runtime.h>
#include <cuda_fp16.h>
#include <math.h>
#include <stdint.h>

// Problem shape (fixed by setup_inputs)
#define N_FEAT  32768
#define M_PROTO 2048
#define K_DIM   512

// ---------------------------------------------------------------------------
// Static device scratch (no cudaMalloc allowed)
// fp16 double-split (x = h0 + h1), pair-permuted per 16-k group:
// phys pair slot j holds logical pair pp[j], pp = {0,4,1,5,2,6,3,7}
// => 8B unit q = logical pairs (q, q+4) = exactly one mma fragment (a0,a2)
// ---------------------------------------------------------------------------
__device__ __half gAh0[(size_t)N_FEAT * K_DIM];
__device__ __half gAh1[(size_t)N_FEAT * K_DIM];
__device__ __half gBh0[(size_t)M_PROTO * K_DIM];
__device__ __half gBh1[(size_t)M_PROTO * K_DIM];
__device__ float g_psq10[M_PROTO];      // 10 * ||p_m||^2

// ---------------------------------------------------------------------------
__device__ __forceinline__ uint32_t smem_u32(const void* p) {
    uint32_t a;
    asm("{ .reg .u64 t; cvta.to.shared.u64 t, %1; cvt.u32.u64 %0, t; }" : "=r"(a) : "l"(p));
    return a;
}
#define CP_ASYNC16(dst, src) \
    asm volatile("cp.async.cg.shared.global [%0], [%1], 16;" :: "r"(dst), "l"(src) : "memory")
#define CP_COMMIT() asm volatile("cp.async.commit_group;" ::: "memory")
#define CP_WAIT(n)  asm volatile("cp.async.wait_group %0;" :: "n"(n) : "memory")

// mma.sync m16n8k16 fp16 with fp32 accumulate (sm_80 baseline)
__device__ __forceinline__ void mma_f16(float* d,
                                        uint32_t a0, uint32_t a1, uint32_t a2, uint32_t a3,
                                        uint32_t b0, uint32_t b1) {
    asm volatile(
        "mma.sync.aligned.m16n8k16.row.col.f32.f16.f16.f32 "
        "{%0,%1,%2,%3}, {%4,%5,%6,%7}, {%8,%9}, {%0,%1,%2,%3};"
        : "+f"(d[0]), "+f"(d[1]), "+f"(d[2]), "+f"(d[3])
        : "r"(a0), "r"(a1), "r"(a2), "r"(a3), "r"(b0), "r"(b1));
}

// ---------------------------------------------------------------------------
// Split fp32 -> fp16 h0 + fp16 h1 (residual), pair-permuted per 16 k.
// One thread = 16 consecutive k of one row.
// For which==1 (prototypes) this kernel ALSO produces g_psq10: 32 groups of
// 16 k = one full row = exactly one warp -> warp shuffle reduction, free.
// ---------------------------------------------------------------------------
__global__ void split_kernel(const float* __restrict__ src, int ngroups, int which) {
    __half* d0 = which ? gBh0 : gAh0;
    __half* d1 = which ? gBh1 : gAh1;
    int g = blockIdx.x * blockDim.x + threadIdx.x;
    if (g >= ngroups) return;

    const float4* s4 = (const float4*)(src + (size_t)g * 16);
    float in[16];
    float4 x0 = s4[0], x1 = s4[1], x2 = s4[2], x3 = s4[3];
    in[0]=x0.x; in[1]=x0.y; in[2]=x0.z; in[3]=x0.w;
    in[4]=x1.x; in[5]=x1.y; in[6]=x1.z; in[7]=x1.w;
    in[8]=x2.x; in[9]=x2.y; in[10]=x2.z; in[11]=x2.w;
    in[12]=x3.x; in[13]=x3.y; in[14]=x3.z; in[15]=x3.w;

    __half h0[16], h1[16];
#pragma unroll
    for (int i = 0; i < 16; i++) {
        h0[i] = __float2half_rn(in[i]);
        h1[i] = __float2half_rn(in[i] - __half2float(h0[i]));
    }

    const int pp[8] = {0, 4, 1, 5, 2, 6, 3, 7};
    __half2 w0[8], w1[8];
#pragma unroll
    for (int j = 0; j < 8; j++) {
        int p = pp[j];
        w0[j] = __halves2half2(h0[2 * p], h0[2 * p + 1]);
        w1[j] = __halves2half2(h1[2 * p], h1[2 * p + 1]);
    }
    uint4* o0 = (uint4*)(d0 + (size_t)g * 16);
    uint4* o1 = (uint4*)(d1 + (size_t)g * 16);
    o0[0] = *(uint4*)&w0[0]; o0[1] = *(uint4*)&w0[4];
    o1[0] = *(uint4*)&w1[0]; o1[1] = *(uint4*)&w1[4];

    // fused 10*||p||^2 for prototypes: warp == row (32 groups x 16 k = 512)
    if (which) {
        float s = 0.f;
#pragma unroll
        for (int i = 0; i < 16; i++) s += in[i] * in[i];
#pragma unroll
        for (int o = 16; o > 0; o >>= 1) s += __shfl_xor_sync(0xFFFFFFFFu, s, o);
        if ((threadIdx.x & 31) == 0) g_psq10[g >> 5] = 10.f * s;
    }
}

// ---------------------------------------------------------------------------
// GEMM: S[n,m] = 20 * dot(feat_n, proto_m) - 10*||p_m||^2
// fp16 double-split emulation: cross = h0h0 + h0h1 + h1h0 (3 mma/tile/k16).
// CTA tile 128 (feat) x 256 (proto), warp tile 64x64 (2M x 4N warps),
// BK=64 (8 iterations, 384 MMAs per barrier interval), 2-stage cp.async ring.
// Stage layout (words): Ah0[0,4096) Ah1[4096,8192) Bh0[8192,16384) Bh1[16384,24576)
// Rows: 64 fp16 = 32 words; 2-bit XOR swizzle on word bits 3-4,
// enumerated conflict-free for frag LDS.64 and 16B store phases.
// ---------------------------------------------------------------------------
#define STAGE_W   24576
#define STAGE_B   (STAGE_W * 4)
#define SMEM_TOT  (2 * STAGE_B)           // 196608 bytes
#define KT_STEPS  (K_DIM / 64)            // 8

__device__ __forceinline__ int swzr(int row) {
    return ((row & 1) << 4) | (((row >> 1) & 1) << 3);
}
__device__ __forceinline__ int wf(int row, int g, int q2) {
    return row * 32 + ((g * 8 + q2) ^ swzr(row));
}

__global__ __launch_bounds__(256, 1)
void gemm_tc_kernel(float* __restrict__ S) {
    extern __shared__ float smem[];
    const uint32_t smem_base = smem_u32(smem);
    const int tid  = threadIdx.x;
    const int wid  = tid >> 5;
    const int lane = tid & 31;
    const int warpM = wid & 1;            // 2 warps in M (feat), 64 rows each
    const int warpN = wid >> 1;           // 4 warps in N (proto), 64 cols each
    const int m0 = blockIdx.x * 256;
    const int n0 = blockIdx.y * 128;

    float acc[4][8][4];
#pragma unroll
    for (int i = 0; i < 4; i++)
#pragma unroll
        for (int j = 0; j < 8; j++)
#pragma unroll
            for (int q = 0; q < 4; q++) acc[i][j][q] = 0.f;

    // ---- stage loader: 24 cp.async(16B) per thread (6144 chunks total) ----
    auto load_stage = [&](int buf, int kt) {
        uint32_t sb = smem_base + (uint32_t)buf * STAGE_B;
#pragma unroll
        for (int it = 0; it < 24; it++) {
            int chunk = tid + it * 256;
            const char* srcb;
            uint32_t dst;
            if (it < 8) {                            // A tiles: 2048 chunks
                int arr = chunk >> 10;               // 0:Ah0 1:Ah1
                int cc  = chunk & 1023;
                int row = cc >> 3, c = cc & 7;
                dst = sb + (uint32_t)(arr * 4096 + row * 32 +
                                      ((4 * c) ^ swzr(row))) * 4u;
                const __half* gsrc = arr ? gAh1 : gAh0;
                srcb = (const char*)gsrc + ((size_t)(n0 + row) * K_DIM + kt * 64) * 2 + c * 16;
            } else {                                 // B tiles: 4096 chunks
                int idx = chunk - 2048;
                int arr = idx >> 11;                 // 0:Bh0 1:Bh1
                int cc  = idx & 2047;
                int row = cc >> 3, c = cc & 7;       // row 0..255
                dst = sb + (uint32_t)(8192 + arr * 8192 + row * 32 +
                                      ((4 * c) ^ swzr(row))) * 4u;
                const __half* gsrc = arr ? gBh1 : gBh0;
                srcb = (const char*)gsrc + ((size_t)(m0 + row) * K_DIM + kt * 64) * 2 + c * 16;
            }
            CP_ASYNC16(dst, srcb);
        }
        CP_COMMIT();
    };

    load_stage(0, 0);
    load_stage(1, 1);

    const int r  = lane >> 2;
    const int q2 = (lane & 3) * 2;

    for (int kt = 0; kt < KT_STEPS; kt++) {
        const int b = kt & 1;
        CP_WAIT(1);
        __syncthreads();

        const float* st  = smem + b * STAGE_W;
        const float* sA0 = st;
        const float* sA1 = st + 4096;
        const float* sB0 = st + 8192;
        const float* sB1 = st + 16384;

#pragma unroll
        for (int g = 0; g < 4; g++) {               // four k16 groups in BK=64
            uint2 BH[8], BL[8];
#pragma unroll
            for (int nt = 0; nt < 8; nt++) {
                int col = warpN * 64 + nt * 8 + r;
                BH[nt] = *(const uint2*)(sB0 + wf(col, g, q2));
                BL[nt] = *(const uint2*)(sB1 + wf(col, g, q2));
            }
#pragma unroll
            for (int mt = 0; mt < 4; mt++) {
                int row = warpM * 64 + mt * 16 + r;
                uint2 ah0 = *(const uint2*)(sA0 + wf(row, g, q2));
                uint2 ah1 = *(const uint2*)(sA0 + wf(row + 8, g, q2));
                uint2 al0 = *(const uint2*)(sA1 + wf(row, g, q2));
                uint2 al1 = *(const uint2*)(sA1 + wf(row + 8, g, q2));
#pragma unroll
                for (int nt = 0; nt < 8; nt++) {
                    // h0*h0
                    mma_f16(acc[mt][nt], ah0.x, ah1.x, ah0.y, ah1.y,
                            BH[nt].x, BH[nt].y);
                    // h0*h1
                    mma_f16(acc[mt][nt], ah0.x, ah1.x, ah0.y, ah1.y,
                            BL[nt].x, BL[nt].y);
                    // h1*h0
                    mma_f16(acc[mt][nt], al0.x, al1.x, al0.y, al1.y,
                            BH[nt].x, BH[nt].y);
                }
            }
        }

        __syncthreads();
        if (kt + 2 < KT_STEPS) load_stage(b, kt + 2);
    }

    // ---- epilogue ----
    float* sp = smem;
    __syncthreads();
    sp[tid] = g_psq10[m0 + tid];        // 256 threads load 256 psq values
    __syncthreads();

#pragma unroll
    for (int mt = 0; mt < 4; mt++) {
        int gr = n0 + warpM * 64 + mt * 16 + r;
#pragma unroll
        for (int nt = 0; nt < 8; nt++) {
            int lc = warpN * 64 + nt * 8 + q2;
            float p0 = sp[lc], p1 = sp[lc + 1];
            float2 o0, o1;
            o0.x = 20.f * acc[mt][nt][0] - p0;
            o0.y = 20.f * acc[mt][nt][1] - p1;
            o1.x = 20.f * acc[mt][nt][2] - p0;
            o1.y = 20.f * acc[mt][nt][3] - p1;
            *(float2*)(S + (size_t)gr * M_PROTO + m0 + lc) = o0;
            *(float2*)(S + (size_t)(gr + 8) * M_PROTO + m0 + lc) = o1;
        }
    }
}

// ---------------------------------------------------------------------------
// Row softmax (in place), quality = 1/sum(exp), max_id = first argmax.
// Shuffle-based reductions (2 block barriers per row instead of 16);
// streaming stores for probs (never re-read -> bypass L2 retention).
// ---------------------------------------------------------------------------
__global__ void softmax_kernel(float* __restrict__ S,
                               float* __restrict__ quality,
                               float* __restrict__ maxid) {
    const int row = blockIdx.x;
    float* srow = S + (size_t)row * M_PROTO;
    const int t = threadIdx.x;
    const int w = t >> 5;
    const int lane = t & 31;

    float v[8];
    float4 v0 = *(const float4*)(srow + t * 8 + 0);
    float4 v1 = *(const float4*)(srow + t * 8 + 4);
    v[0] = v0.x; v[1] = v0.y; v[2] = v0.z; v[3] = v0.w;
    v[4] = v1.x; v[5] = v1.y; v[6] = v1.z; v[7] = v1.w;

    float lmax = v[0];
    int   limx = t * 8;
#pragma unroll
    for (int j = 1; j < 8; j++)
        if (v[j] > lmax) { lmax = v[j]; limx = t * 8 + j; }

    // warp-level argmax (strict >; tie -> lower index)
#pragma unroll
    for (int o = 16; o > 0; o >>= 1) {
        float m2 = __shfl_xor_sync(0xFFFFFFFFu, lmax, o);
        int   i2 = __shfl_xor_sync(0xFFFFFFFFu, limx, o);
        if (m2 > lmax || (m2 == lmax && i2 < limx)) { lmax = m2; limx = i2; }
    }

    __shared__ float swm[8];
    __shared__ int   swi[8];
    __shared__ float sbc[2];            // broadcast: rowmax, invsum
    __shared__ int   sbi;
    if (lane == 0) { swm[w] = lmax; swi[w] = limx; }
    __syncthreads();
    if (t == 0) {
        float bm = swm[0]; int bi = swi[0];
#pragma unroll
        for (int k = 1; k < 8; k++) {
            if (swm[k] > bm || (swm[k] == bm && swi[k] < bi)) { bm = swm[k]; bi = swi[k]; }
        }
        sbc[0] = bm; sbi = bi;
    }
    __syncthreads();
    const float rowmax = sbc[0];

    float e[8];
    float lsum = 0.f;
#pragma unroll
    for (int j = 0; j < 8; j++) { e[j] = expf(v[j] - rowmax); lsum += e[j]; }
#pragma unroll
    for (int o = 16; o > 0; o >>= 1) lsum += __shfl_xor_sync(0xFFFFFFFFu, lsum, o);
    if (lane == 0) swm[w] = lsum;
    __syncthreads();
    if (t == 0) {
        float s = swm[0];
#pragma unroll
        for (int k = 1; k < 8; k++) s += swm[k];
        sbc[1] = 1.0f / s;
    }
    __syncthreads();
    const float inv = sbc[1];

    float4 o0, o1;
    o0.x = e[0] * inv; o0.y = e[1] * inv; o0.z = e[2] * inv; o0.w = e[3] * inv;
    o1.x = e[4] * inv; o1.y = e[5] * inv; o1.z = e[6] * inv; o1.w = e[7] * inv;
    __stcs((float4*)(srow + t * 8 + 0), o0);
    __stcs((float4*)(srow + t * 8 + 4), o1);

    if (t == 0) {
        quality[row] = inv;
        maxid[row]   = (float)sbi;
    }
}

// ---------------------------------------------------------------------------
extern "C" void kernel_launch(void* const* d_in, const int* in_sizes, int n_in,
                              void* d_out, int out_size) {
    const float* feat  = (const float*)d_in[0];   // [32768, 512]
    const float* proto = (const float*)d_in[1];   // [2048, 512]
    float* out = (float*)d_out;

    float* quality = out;
    float* maxid   = out + N_FEAT;
    float* pred    = out + 2 * N_FEAT;

    cudaFuncSetAttribute(gemm_tc_kernel,
                         cudaFuncAttributeMaxDynamicSharedMemorySize, SMEM_TOT);

    int gA = N_FEAT * K_DIM / 16;
    int gB = M_PROTO * K_DIM / 16;
    split_kernel<<<(gA + 255) / 256, 256>>>(feat, gA, 0);
    split_kernel<<<(gB + 255) / 256, 256>>>(proto, gB, 1);   // + fused psq

    dim3 grid(M_PROTO / 256, N_FEAT / 128);
    gemm_tc_kernel<<<grid, 256, SMEM_TOT>>>(pred);

    softmax_kernel<<<N_FEAT, 256>>>(pred, quality, maxid);
}